// round 8
// baseline (speedup 1.0000x reference)
#include <cuda_runtime.h>

// DifferentiableNERF, round 8.
// SEG=8: 64 threads per chain, 2 chains per 128-thread block.
// R7 + ONE mid-segment Gram-Schmidt: the unnormalized frame update's scale
// defect grows ~1.4x per placed atom (ey' = ez' x u sums the other axes'
// defects), so drift windows must stay <= 12 atoms (4 residues) — the regime
// validated in R6. GS after residue 4 and at segment end.

namespace {

constexpr int L_CONST = 512;
constexpr int NSTEP = L_CONST - 1;   // 511
constexpr int SEG = 8;               // steps per thread
constexpr int TPC = 64;              // threads per chain
constexpr int THREADS = 128;         // 2 chains per block
constexpr int CHAIN_FLOATS = 3 * L_CONST * 3;  // 4608
constexpr int ROWS = SEG * 9;        // 72
constexpr int COLS = THREADS + 1;    // 129 (conflict-free stride)

struct V3 { float x, y, z; };

__device__ __forceinline__ V3 vsub(V3 a, V3 b) { return {a.x - b.x, a.y - b.y, a.z - b.z}; }
__device__ __forceinline__ V3 vcross(V3 a, V3 b) {
    return { a.y * b.z - a.z * b.y,
             a.z * b.x - a.x * b.z,
             a.x * b.y - a.y * b.x };
}
__device__ __forceinline__ float vdot(V3 a, V3 b) { return a.x * b.x + a.y * b.y + a.z * b.z; }
__device__ __forceinline__ V3 vunit(V3 a) {
    float r = rsqrtf(fmaxf(vdot(a, a), 1e-30f));
    return { a.x * r, a.y * r, a.z * r };
}

struct Aff { float m[9]; float t[3]; };

__device__ __forceinline__ Aff identityAff() {
    Aff r;
    r.m[0] = 1.f; r.m[1] = 0.f; r.m[2] = 0.f;
    r.m[3] = 0.f; r.m[4] = 1.f; r.m[5] = 0.f;
    r.m[6] = 0.f; r.m[7] = 0.f; r.m[8] = 1.f;
    r.t[0] = 0.f; r.t[1] = 0.f; r.t[2] = 0.f;
    return r;
}

// (A o B)(x) = A(B(x))
__device__ __forceinline__ Aff compose(const Aff& A, const Aff& B) {
    Aff r;
#pragma unroll
    for (int i = 0; i < 3; i++) {
#pragma unroll
        for (int j = 0; j < 3; j++) {
            r.m[3 * i + j] = A.m[3 * i + 0] * B.m[0 + j]
                           + A.m[3 * i + 1] * B.m[3 + j]
                           + A.m[3 * i + 2] * B.m[6 + j];
        }
        r.t[i] = A.m[3 * i + 0] * B.t[0]
               + A.m[3 * i + 1] * B.t[1]
               + A.m[3 * i + 2] * B.t[2] + A.t[i];
    }
    return r;
}

__device__ __forceinline__ Aff invRigid(const Aff& A) {
    Aff r;
    r.m[0] = A.m[0]; r.m[1] = A.m[3]; r.m[2] = A.m[6];
    r.m[3] = A.m[1]; r.m[4] = A.m[4]; r.m[5] = A.m[7];
    r.m[6] = A.m[2]; r.m[7] = A.m[5]; r.m[8] = A.m[8];
#pragma unroll
    for (int i = 0; i < 3; i++) {
        r.t[i] = -(r.m[3 * i + 0] * A.t[0] + r.m[3 * i + 1] * A.t[1] + r.m[3 * i + 2] * A.t[2]);
    }
    return r;
}

// Orthonormal placement frame: ex = bond dir, ez = plane normal, ey = ez x ex.
struct Frame { V3 ex, ey, ez; V3 c; };

__device__ __forceinline__ V3 placeF(Frame& F, float ang, float len, float tor) {
    float st, ct, sa, ca;
    __sincosf(tor, &st, &ct);
    __sincosf(ang, &sa, &ca);
    float k2 = ct * sa, k3 = st * sa;
    V3 u  = { k3 * F.ez.x + (k2 * F.ey.x - ca * F.ex.x),
              k3 * F.ez.y + (k2 * F.ey.y - ca * F.ex.y),
              k3 * F.ez.z + (k2 * F.ey.z - ca * F.ex.z) };
    V3 p  = { F.c.x + len * u.x, F.c.y + len * u.y, F.c.z + len * u.z };
    V3 ez2 = { ct * F.ez.x - st * F.ey.x,
               ct * F.ez.y - st * F.ey.y,
               ct * F.ez.z - st * F.ey.z };
    V3 ey2 = vcross(ez2, u);
    F.ex = u; F.ey = ey2; F.ez = ez2; F.c = p;
    return p;
}

__device__ __forceinline__ Frame frameOfTriplet(V3 a, V3 b, V3 c) {
    Frame F;
    F.ex = vunit(vsub(c, b));
    F.ez = vunit(vcross(vsub(b, a), F.ex));
    F.ey = vcross(F.ez, F.ex);
    F.c = c;
    return F;
}

// Gram-Schmidt: restore exact orthonormality of the propagated frame.
__device__ __forceinline__ void orthonormalize(Frame& F) {
    V3 ex = vunit(F.ex);
    float d = vdot(F.ez, ex);
    V3 ez = { F.ez.x - d * ex.x, F.ez.y - d * ex.y, F.ez.z - d * ex.z };
    ez = vunit(ez);
    F.ex = ex;
    F.ez = ez;
    F.ey = vcross(ez, ex);
}

__device__ __forceinline__ Aff frameToAff(const Frame& F) {
    Aff A;
    A.m[0] = F.ex.x; A.m[1] = F.ey.x; A.m[2] = F.ez.x;
    A.m[3] = F.ex.y; A.m[4] = F.ey.y; A.m[5] = F.ez.y;
    A.m[6] = F.ex.z; A.m[7] = F.ey.z; A.m[8] = F.ez.z;
    A.t[0] = F.c.x;  A.t[1] = F.c.y;  A.t[2] = F.c.z;
    return A;
}

__device__ __forceinline__ Aff shflUpAff(const Aff& A, int delta) {
    Aff r;
#pragma unroll
    for (int k = 0; k < 9; k++) r.m[k] = __shfl_up_sync(0xffffffffu, A.m[k], delta);
#pragma unroll
    for (int k = 0; k < 3; k++) r.t[k] = __shfl_up_sync(0xffffffffu, A.t[k], delta);
    return r;
}

__constant__ float c9[9] = {
    17.047f, 14.099f, 3.625f,
    16.967f, 12.784f, 4.338f,
    15.685f, 12.755f, 5.133f
};

__global__ __launch_bounds__(THREADS, 6)
void nerf_kernel(const float* __restrict__ phi,
                 const float* __restrict__ psi,
                 const float* __restrict__ omega,
                 const float* __restrict__ bl,
                 const float* __restrict__ ba,
                 float* __restrict__ out) {
    __shared__ float traj[ROWS][COLS];
    __shared__ float warpTot[2][12];   // per-chain first-warp inclusive total

    const int tid  = threadIdx.x;
    const int lane = tid & 31;
    const int warp = tid >> 5;
    const int u    = tid & 63;         // thread within chain
    const int cl   = tid >> 6;         // chain slot in block (0/1)
    const int chain = blockIdx.x * 2 + cl;

    const int base = u * SEG;

    const V3 A0 = {17.047f, 14.099f, 3.625f};
    const V3 B0 = {16.967f, 12.784f, 4.338f};
    const V3 C0 = {15.685f, 12.755f, 5.133f};

    const float* __restrict__ phiR = phi   + (size_t)chain * L_CONST;
    const float* __restrict__ psiS = psi   + (size_t)chain * L_CONST + base;
    const float* __restrict__ omgS = omega + (size_t)chain * L_CONST + base;
    const float* __restrict__ blS  = bl + (size_t)chain * L_CONST * 3 + 3 * base;
    const float* __restrict__ baS  = ba + (size_t)chain * L_CONST * 3 + 3 * base;

    // ---- phi for this thread's 8 steps: phi[base+1 .. base+8] ----
    float4 phq0 = *(const float4*)(phiR + base);
    float4 phq1 = *(const float4*)(phiR + base + 4);
    float ph8 = __shfl_down_sync(0xffffffffu, phq0.x, 1);   // next thread's phi[base]
    if (lane == 31) {
        int ip = base + SEG;
        if (ip > NSTEP) ip = NSTEP;     // only u=63; value unused there
        ph8 = phiR[ip];
    }
    float phv[8] = { phq0.y, phq0.z, phq0.w, phq1.x, phq1.y, phq1.z, phq1.w, ph8 };

    // ---- Pass 1: closed-form frame propagation from canonical init ----
    Frame Fr = frameOfTriplet(A0, B0, C0);
#pragma unroll
    for (int g = 0; g < 2; g++) {
        float4 psq = *(const float4*)(psiS + 4 * g);
        float4 omq = *(const float4*)(omgS + 4 * g);
        float4 blq[3], baq[3];
#pragma unroll
        for (int q = 0; q < 3; q++) {
            blq[q] = *(const float4*)(blS + 12 * g + 4 * q);
            baq[q] = *(const float4*)(baS + 12 * g + 4 * q);
        }
        const float* psf = (const float*)&psq;
        const float* omf = (const float*)&omq;
        const float* blf = (const float*)blq;
        const float* baf = (const float*)baq;
#pragma unroll
        for (int t = 0; t < 4; t++) {
            int s = 4 * g + t;
            int i = base + s;
            if (i < NSTEP) {
                V3 p1 = placeF(Fr, baf[3 * t + 1], blf[3 * t + 2], psf[t]);
                V3 p2 = placeF(Fr, baf[3 * t + 2], blf[3 * t + 0], omf[t]);
                V3 p3 = placeF(Fr, baf[3 * t + 0], blf[3 * t + 1], phv[s]);
                traj[9 * s + 0][tid] = p1.x; traj[9 * s + 1][tid] = p1.y; traj[9 * s + 2][tid] = p1.z;
                traj[9 * s + 3][tid] = p2.x; traj[9 * s + 4][tid] = p2.y; traj[9 * s + 5][tid] = p2.z;
                traj[9 * s + 6][tid] = p3.x; traj[9 * s + 7][tid] = p3.y; traj[9 * s + 8][tid] = p3.z;
            }
        }
        // Mid-segment drift reset: the frame scale defect grows ~1.4x per
        // atom; cap unnormalized windows at 12 atoms (R6-validated regime).
        orthonormalize(Fr);
    }

    // ---- Conjugated segment transform: H' = F(end) o F0^-1 ----
    const Aff F0i = invRigid(frameToAff(frameOfTriplet(A0, B0, C0)));
    Aff P = compose(frameToAff(Fr), F0i);

    // Warp inclusive Kogge-Stone scan (warp == half-chain; lanes in order).
#pragma unroll
    for (int off = 1; off < 32; off <<= 1) {
        Aff prev = shflUpAff(P, off);
        Aff comb = compose(prev, P);
        if (lane >= off) P = comb;
    }

    // First warp of each chain publishes its inclusive total.
    if (lane == 31 && (warp & 1) == 0) {
#pragma unroll
        for (int k = 0; k < 9; k++) warpTot[cl][k] = P.m[k];
#pragma unroll
        for (int k = 0; k < 3; k++) warpTot[cl][9 + k] = P.t[k];
    }

    Aff Pex = shflUpAff(P, 1);   // warp-local exclusive prefix
    __syncthreads();

    // Per-thread world transform W (exclusive prefix in conjugated space).
    Aff W;
    if ((warp & 1) == 0) {
        W = (lane == 0) ? identityAff() : Pex;
    } else {
        Aff T;
#pragma unroll
        for (int k = 0; k < 9; k++) T.m[k] = warpTot[cl][k];
#pragma unroll
        for (int k = 0; k < 3; k++) T.t[k] = warpTot[cl][9 + k];
        W = (lane == 0) ? T : compose(T, Pex);
    }

    // ---- Pass 2: transform local trajectory in SMEM ----
#pragma unroll
    for (int s = 0; s < SEG; s++) {
#pragma unroll
        for (int p = 0; p < 3; p++) {
            V3 v;
            v.x = traj[9 * s + 3 * p + 0][tid];
            v.y = traj[9 * s + 3 * p + 1][tid];
            v.z = traj[9 * s + 3 * p + 2][tid];
            float wx = W.m[0] * v.x + W.m[1] * v.y + W.m[2] * v.z + W.t[0];
            float wy = W.m[3] * v.x + W.m[4] * v.y + W.m[5] * v.z + W.t[1];
            float wz = W.m[6] * v.x + W.m[7] * v.y + W.m[8] * v.z + W.t[2];
            traj[9 * s + 3 * p + 0][tid] = wx;
            traj[9 * s + 3 * p + 1][tid] = wy;
            traj[9 * s + 3 * p + 2][tid] = wz;
        }
    }
    __syncthreads();

    // ---- Writeout: coalesced, division-free incremental walk ----
    // out[f] for f = it*64 + u; f>=9: g=f-9, owner=g/ROWS, row=g%ROWS,
    // value = traj[row][64*cl + owner].
    float* __restrict__ outC = out + (size_t)chain * CHAIN_FLOATS;
    const float* trajF = &traj[0][0];
    const int colBase = cl << 6;

    // Iteration 0 (u<9 -> init constants).
    {
        float v;
        if (u < 9) v = c9[u];
        else       v = trajF[(u - 9) * COLS + colBase];
        outC[u] = v;
    }
    int row = (u - 9) + 64;                       // row for iteration 1
    const float* p = trajF + row * COLS + colBase;
    if (row >= ROWS) { row -= ROWS; p -= (ROWS * COLS - 1); }
#pragma unroll 8
    for (int it = 1; it < CHAIN_FLOATS / TPC; it++) {
        outC[it * TPC + u] = *p;
        row += 64;
        p += 64 * COLS;
        if (row >= ROWS) { row -= ROWS; p -= (ROWS * COLS - 1); }
    }
}

} // anonymous namespace

extern "C" void kernel_launch(void* const* d_in, const int* in_sizes, int n_in,
                              void* d_out, int out_size) {
    const float* phi   = (const float*)d_in[0];
    const float* psi   = (const float*)d_in[1];
    const float* omega = (const float*)d_in[2];
    const float* bl    = (const float*)d_in[3];
    const float* ba    = (const float*)d_in[4];

    const int B = in_sizes[0] / L_CONST;

    nerf_kernel<<<B / 2, THREADS>>>(phi, psi, omega, bl, ba, (float*)d_out);
}

// round 9
// speedup vs baseline: 1.2286x; 1.2286x over previous
#include <cuda_runtime.h>

// DifferentiableNERF, round 9.
// R6 configuration restored (SEG=4, 128 threads per chain, transposed
// conflict-free SMEM, closed-form frame propagation with end-of-segment
// Gram-Schmidt, matrix Kogge-Stone scan) — validated at 36.9us / rel_err 3.3e-5.
// R8 showed SEG=8 regresses (serial chain too long to hide at this occupancy).
// New here: division-free incremental writeout walk (owner +3, row +20 mod 36,
// pointer-carried) replacing the per-element g/9 + g/36 address chain.

namespace {

constexpr int L_CONST = 512;
constexpr int NSTEP = L_CONST - 1;   // 511
constexpr int SEG = 4;               // steps per thread
constexpr int THREADS = 128;         // 4 warps = 1 chain
constexpr int CHAIN_FLOATS = 3 * L_CONST * 3;  // 4608
constexpr int ROWS = SEG * 9;        // 36
constexpr int COLS = THREADS + 1;    // 129 (conflict-free stride)

struct V3 { float x, y, z; };

__device__ __forceinline__ V3 vsub(V3 a, V3 b) { return {a.x - b.x, a.y - b.y, a.z - b.z}; }
__device__ __forceinline__ V3 vcross(V3 a, V3 b) {
    return { a.y * b.z - a.z * b.y,
             a.z * b.x - a.x * b.z,
             a.x * b.y - a.y * b.x };
}
__device__ __forceinline__ float vdot(V3 a, V3 b) { return a.x * b.x + a.y * b.y + a.z * b.z; }
__device__ __forceinline__ V3 vunit(V3 a) {
    float r = rsqrtf(fmaxf(vdot(a, a), 1e-30f));
    return { a.x * r, a.y * r, a.z * r };
}

struct Aff { float m[9]; float t[3]; };

__device__ __forceinline__ Aff identityAff() {
    Aff r;
    r.m[0] = 1.f; r.m[1] = 0.f; r.m[2] = 0.f;
    r.m[3] = 0.f; r.m[4] = 1.f; r.m[5] = 0.f;
    r.m[6] = 0.f; r.m[7] = 0.f; r.m[8] = 1.f;
    r.t[0] = 0.f; r.t[1] = 0.f; r.t[2] = 0.f;
    return r;
}

// (A o B)(x) = A(B(x))
__device__ __forceinline__ Aff compose(const Aff& A, const Aff& B) {
    Aff r;
#pragma unroll
    for (int i = 0; i < 3; i++) {
#pragma unroll
        for (int j = 0; j < 3; j++) {
            r.m[3 * i + j] = A.m[3 * i + 0] * B.m[0 + j]
                           + A.m[3 * i + 1] * B.m[3 + j]
                           + A.m[3 * i + 2] * B.m[6 + j];
        }
        r.t[i] = A.m[3 * i + 0] * B.t[0]
               + A.m[3 * i + 1] * B.t[1]
               + A.m[3 * i + 2] * B.t[2] + A.t[i];
    }
    return r;
}

__device__ __forceinline__ Aff invRigid(const Aff& A) {
    Aff r;
    r.m[0] = A.m[0]; r.m[1] = A.m[3]; r.m[2] = A.m[6];
    r.m[3] = A.m[1]; r.m[4] = A.m[4]; r.m[5] = A.m[7];
    r.m[6] = A.m[2]; r.m[7] = A.m[5]; r.m[8] = A.m[8];
#pragma unroll
    for (int i = 0; i < 3; i++) {
        r.t[i] = -(r.m[3 * i + 0] * A.t[0] + r.m[3 * i + 1] * A.t[1] + r.m[3 * i + 2] * A.t[2]);
    }
    return r;
}

// Orthonormal placement frame: ex = bond dir, ez = plane normal, ey = ez x ex.
struct Frame { V3 ex, ey, ez; V3 c; };

__device__ __forceinline__ V3 placeF(Frame& F, float ang, float len, float tor) {
    float st, ct, sa, ca;
    __sincosf(tor, &st, &ct);
    __sincosf(ang, &sa, &ca);
    float k2 = ct * sa, k3 = st * sa;
    V3 u  = { k3 * F.ez.x + (k2 * F.ey.x - ca * F.ex.x),
              k3 * F.ez.y + (k2 * F.ey.y - ca * F.ex.y),
              k3 * F.ez.z + (k2 * F.ey.z - ca * F.ex.z) };
    V3 p  = { F.c.x + len * u.x, F.c.y + len * u.y, F.c.z + len * u.z };
    V3 ez2 = { ct * F.ez.x - st * F.ey.x,
               ct * F.ez.y - st * F.ey.y,
               ct * F.ez.z - st * F.ey.z };
    V3 ey2 = vcross(ez2, u);
    F.ex = u; F.ey = ey2; F.ez = ez2; F.c = p;
    return p;
}

__device__ __forceinline__ Frame frameOfTriplet(V3 a, V3 b, V3 c) {
    Frame F;
    F.ex = vunit(vsub(c, b));
    F.ez = vunit(vcross(vsub(b, a), F.ex));
    F.ey = vcross(F.ez, F.ex);
    F.c = c;
    return F;
}

// Gram-Schmidt: restore exact orthonormality of the propagated frame.
__device__ __forceinline__ void orthonormalize(Frame& F) {
    V3 ex = vunit(F.ex);
    float d = vdot(F.ez, ex);
    V3 ez = { F.ez.x - d * ex.x, F.ez.y - d * ex.y, F.ez.z - d * ex.z };
    ez = vunit(ez);
    F.ex = ex;
    F.ez = ez;
    F.ey = vcross(ez, ex);
}

__device__ __forceinline__ Aff frameToAff(const Frame& F) {
    Aff A;
    A.m[0] = F.ex.x; A.m[1] = F.ey.x; A.m[2] = F.ez.x;
    A.m[3] = F.ex.y; A.m[4] = F.ey.y; A.m[5] = F.ez.y;
    A.m[6] = F.ex.z; A.m[7] = F.ey.z; A.m[8] = F.ez.z;
    A.t[0] = F.c.x;  A.t[1] = F.c.y;  A.t[2] = F.c.z;
    return A;
}

__device__ __forceinline__ Aff shflUpAff(const Aff& A, int delta) {
    Aff r;
#pragma unroll
    for (int k = 0; k < 9; k++) r.m[k] = __shfl_up_sync(0xffffffffu, A.m[k], delta);
#pragma unroll
    for (int k = 0; k < 3; k++) r.t[k] = __shfl_up_sync(0xffffffffu, A.t[k], delta);
    return r;
}

__constant__ float c9[9] = {
    17.047f, 14.099f, 3.625f,
    16.967f, 12.784f, 4.338f,
    15.685f, 12.755f, 5.133f
};

__global__ __launch_bounds__(THREADS, 7)
void nerf_kernel(const float* __restrict__ phi,
                 const float* __restrict__ psi,
                 const float* __restrict__ omega,
                 const float* __restrict__ bl,
                 const float* __restrict__ ba,
                 float* __restrict__ out) {
    __shared__ float traj[ROWS][COLS];
    __shared__ float warpTot[3][12];   // inclusive totals of warps 0..2

    const int tid  = threadIdx.x;
    const int lane = tid & 31;
    const int warp = tid >> 5;
    const int chain = blockIdx.x;

    const int base = tid * SEG;

    const V3 A0 = {17.047f, 14.099f, 3.625f};
    const V3 B0 = {16.967f, 12.784f, 4.338f};
    const V3 C0 = {15.685f, 12.755f, 5.133f};

    const float* __restrict__ phiR = phi   + (size_t)chain * L_CONST;
    const float* __restrict__ psiS = psi   + (size_t)chain * L_CONST + base;
    const float* __restrict__ omgS = omega + (size_t)chain * L_CONST + base;
    const float* __restrict__ blS  = bl + (size_t)chain * L_CONST * 3 + 3 * base;
    const float* __restrict__ baS  = ba + (size_t)chain * L_CONST * 3 + 3 * base;

    // ---- Batched vector loads of this thread's 4-step inputs ----
    float4 psq = *(const float4*)psiS;
    float4 omq = *(const float4*)omgS;
    float4 blq[3], baq[3];
#pragma unroll
    for (int q = 0; q < 3; q++) {
        blq[q] = *(const float4*)(blS + 4 * q);
        baq[q] = *(const float4*)(baS + 4 * q);
    }
    float4 phq = *(const float4*)(phiR + base);   // phi[base .. base+3]
    float ph3 = __shfl_down_sync(0xffffffffu, phq.x, 1);   // phi[base+4]
    if (lane == 31) {
        int ip = base + SEG;
        ph3 = (ip < L_CONST) ? phiR[ip] : 0.f;
    }
    float phv[4] = { phq.y, phq.z, phq.w, ph3 };
    const float* psf = (const float*)&psq;
    const float* omf = (const float*)&omq;
    const float* blf = (const float*)blq;
    const float* baf = (const float*)baq;

    // ---- Pass 1: closed-form frame propagation from canonical init ----
    Frame Fr = frameOfTriplet(A0, B0, C0);
#pragma unroll
    for (int t = 0; t < SEG; t++) {
        int i = base + t;
        if (i < NSTEP) {
            V3 p1 = placeF(Fr, baf[3 * t + 1], blf[3 * t + 2], psf[t]);
            V3 p2 = placeF(Fr, baf[3 * t + 2], blf[3 * t + 0], omf[t]);
            V3 p3 = placeF(Fr, baf[3 * t + 0], blf[3 * t + 1], phv[t]);
            traj[9 * t + 0][tid] = p1.x; traj[9 * t + 1][tid] = p1.y; traj[9 * t + 2][tid] = p1.z;
            traj[9 * t + 3][tid] = p2.x; traj[9 * t + 4][tid] = p2.y; traj[9 * t + 5][tid] = p2.z;
            traj[9 * t + 6][tid] = p3.x; traj[9 * t + 7][tid] = p3.y; traj[9 * t + 8][tid] = p3.z;
        }
    }

    // Scan inputs must be exact rotations (R6/R8 lesson): GS the endpoint.
    orthonormalize(Fr);

    // ---- Conjugated segment transform: H' = F(end) o F0^-1 ----
    const Aff F0i = invRigid(frameToAff(frameOfTriplet(A0, B0, C0)));
    Aff P = compose(frameToAff(Fr), F0i);

    // Warp inclusive Kogge-Stone scan
#pragma unroll
    for (int off = 1; off < 32; off <<= 1) {
        Aff prev = shflUpAff(P, off);
        Aff comb = compose(prev, P);
        if (lane >= off) P = comb;
    }

    // Publish warp totals
    if (lane == 31 && warp < 3) {
#pragma unroll
        for (int k = 0; k < 9; k++) warpTot[warp][k] = P.m[k];
#pragma unroll
        for (int k = 0; k < 3; k++) warpTot[warp][9 + k] = P.t[k];
    }

    Aff Pex = shflUpAff(P, 1);   // warp-local exclusive prefix
    __syncthreads();

    // W = warpTot[0] o ... o warpTot[warp-1] o Pex   (exclusive prefix = W)
    Aff W = (lane == 0) ? identityAff() : Pex;
    for (int v = warp - 1; v >= 0; v--) {
        Aff T;
#pragma unroll
        for (int k = 0; k < 9; k++) T.m[k] = warpTot[v][k];
#pragma unroll
        for (int k = 0; k < 3; k++) T.t[k] = warpTot[v][9 + k];
        W = compose(T, W);
    }

    // ---- Pass 2: transform local trajectory in SMEM ----
#pragma unroll
    for (int s = 0; s < SEG; s++) {
#pragma unroll
        for (int p = 0; p < 3; p++) {
            V3 v;
            v.x = traj[9 * s + 3 * p + 0][tid];
            v.y = traj[9 * s + 3 * p + 1][tid];
            v.z = traj[9 * s + 3 * p + 2][tid];
            float wx = W.m[0] * v.x + W.m[1] * v.y + W.m[2] * v.z + W.t[0];
            float wy = W.m[3] * v.x + W.m[4] * v.y + W.m[5] * v.z + W.t[1];
            float wz = W.m[6] * v.x + W.m[7] * v.y + W.m[8] * v.z + W.t[2];
            traj[9 * s + 3 * p + 0][tid] = wx;
            traj[9 * s + 3 * p + 1][tid] = wy;
            traj[9 * s + 3 * p + 2][tid] = wz;
        }
    }
    __syncthreads();

    // ---- Writeout: coalesced, division-free incremental walk ----
    // out[f], f = it*128 + tid. f>=9: g=f-9, owner=g/36, row=g%36,
    // value = traj[row][owner]. Per iteration: g += 128 => owner += 3,
    // row += 20, single conditional wrap (20 < 36 so at most one).
    float* __restrict__ outC = out + (size_t)chain * CHAIN_FLOATS;
    const float* trajF = &traj[0][0];

    // Iteration 0 (tid<9 -> init constants).
    {
        float v;
        if (tid < 9) {
            v = c9[tid];
        } else {
            int g0 = tid - 9;
            int ow0 = g0 / 36;
            int rw0 = g0 - 36 * ow0;
            v = trajF[rw0 * COLS + ow0];
        }
        outC[tid] = v;
    }
    // Walk state for iteration 1: g1 = tid + 119.
    int g1 = tid + 119;
    int ow = g1 / 36;
    int rw = g1 - 36 * ow;
    const float* p = trajF + rw * COLS + ow;
#pragma unroll
    for (int it = 1; it < CHAIN_FLOATS / THREADS; it++) {
        outC[it * THREADS + tid] = *p;
        rw += 20;
        p += 20 * COLS + 3;
        if (rw >= ROWS) { rw -= ROWS; p -= (ROWS * COLS - 1); }
    }
}

} // anonymous namespace

extern "C" void kernel_launch(void* const* d_in, const int* in_sizes, int n_in,
                              void* d_out, int out_size) {
    const float* phi   = (const float*)d_in[0];
    const float* psi   = (const float*)d_in[1];
    const float* omega = (const float*)d_in[2];
    const float* bl    = (const float*)d_in[3];
    const float* ba    = (const float*)d_in[4];

    const int B = in_sizes[0] / L_CONST;

    nerf_kernel<<<B, THREADS>>>(phi, psi, omega, bl, ba, (float*)d_out);
}